// round 2
// baseline (speedup 1.0000x reference)
#include <cuda_runtime.h>
#include <cuda_bf16.h>
#include <cstdint>
#include <math.h>

#define EMBED 1024
#define HIDDEN 4096
#define NEXP 8
#define NTOK 1024
#define MAXROWS 2048   // NTOK * TOP_K

// ---------------- device scratch ----------------
__device__ float g_h[MAXROWS * HIDDEN];          // 32 MB: gelu(x@w1+b1), compacted rows
__device__ float g_slot[NTOK * 2 * EMBED];       // 8 MB: per (token, k) expert output
__device__ float g_topw[NTOK * 2];               // renormalized top-2 gate weights
__device__ int   g_tok[NEXP * MAXROWS];          // per-expert gathered token ids
__device__ int   g_kslot[NEXP * MAXROWS];        // which of the 2 slots this row fills
__device__ int   g_count[NEXP];
__device__ int   g_offset[NEXP];

// ---------------- small kernels ----------------
__global__ void init_kernel() {
    if (threadIdx.x < NEXP) g_count[threadIdx.x] = 0;
}

__global__ void router_kernel(const float* __restrict__ x, const float* __restrict__ gw) {
    int warp = (blockIdx.x * blockDim.x + threadIdx.x) >> 5;
    int lane = threadIdx.x & 31;
    if (warp >= NTOK) return;
    const float* xr = x + (size_t)warp * EMBED;
    float acc[NEXP];
#pragma unroll
    for (int n = 0; n < NEXP; n++) acc[n] = 0.f;
    for (int d = lane; d < EMBED; d += 32) {
        float xv = xr[d];
#pragma unroll
        for (int n = 0; n < NEXP; n++) acc[n] += xv * gw[n * EMBED + d];
    }
#pragma unroll
    for (int n = 0; n < NEXP; n++)
#pragma unroll
        for (int o = 16; o > 0; o >>= 1) acc[n] += __shfl_xor_sync(0xffffffffu, acc[n], o);
    if (lane == 0) {
        float mx = acc[0];
#pragma unroll
        for (int n = 1; n < NEXP; n++) mx = fmaxf(mx, acc[n]);
        float p[NEXP], s = 0.f;
#pragma unroll
        for (int n = 0; n < NEXP; n++) { p[n] = expf(acc[n] - mx); s += p[n]; }
        float inv = 1.f / s;
#pragma unroll
        for (int n = 0; n < NEXP; n++) p[n] *= inv;
        int i0 = 0;
#pragma unroll
        for (int n = 1; n < NEXP; n++) if (p[n] > p[i0]) i0 = n;
        int i1 = (i0 == 0) ? 1 : 0;
#pragma unroll
        for (int n = 0; n < NEXP; n++) if (n != i0 && p[n] > p[i1]) i1 = n;
        float w0 = p[i0], w1 = p[i1];
        float rs = 1.f / (w0 + w1 + 1e-9f);
        g_topw[warp * 2 + 0] = w0 * rs;
        g_topw[warp * 2 + 1] = w1 * rs;
        int pos0 = atomicAdd(&g_count[i0], 1);
        g_tok[i0 * MAXROWS + pos0] = warp; g_kslot[i0 * MAXROWS + pos0] = 0;
        int pos1 = atomicAdd(&g_count[i1], 1);
        g_tok[i1 * MAXROWS + pos1] = warp; g_kslot[i1 * MAXROWS + pos1] = 1;
    }
}

__global__ void offsets_kernel() {
    if (threadIdx.x == 0) {
        int o = 0;
        for (int e = 0; e < NEXP; e++) { g_offset[e] = o; o += g_count[e]; }
    }
}

// ---------------- helpers ----------------
__device__ __forceinline__ float gelu_exact(float v) {
    return 0.5f * v * (1.0f + erff(v * 0.7071067811865476f));
}

__device__ __forceinline__ void cp16(float* dst_smem, const void* src, bool pred) {
    uint32_t d = (uint32_t)__cvta_generic_to_shared(dst_smem);
    int sz = pred ? 16 : 0;  // src-size 0 => zero-fill the 16B
    asm volatile("cp.async.cg.shared.global [%0], [%1], 16, %2;\n" ::"r"(d), "l"(src), "r"(sz));
}

// split two fp32 into packed bf16x2 (hi) + packed bf16x2 (lo residual)
__device__ __forceinline__ void split2(float x, float y, uint32_t& hi, uint32_t& lo) {
    __nv_bfloat162 h = __floats2bfloat162_rn(x, y);   // low half = x
    float rx = x - __bfloat162float(h.x);
    float ry = y - __bfloat162float(h.y);
    __nv_bfloat162 l = __floats2bfloat162_rn(rx, ry);
    hi = *reinterpret_cast<uint32_t*>(&h);
    lo = *reinterpret_cast<uint32_t*>(&l);
}

__device__ __forceinline__ void mma_bf16(float c[4], const uint32_t a[4], const uint32_t b[2]) {
    asm volatile(
        "mma.sync.aligned.m16n8k16.row.col.f32.bf16.bf16.f32 "
        "{%0,%1,%2,%3}, {%4,%5,%6,%7}, {%8,%9}, {%0,%1,%2,%3};\n"
        : "+f"(c[0]), "+f"(c[1]), "+f"(c[2]), "+f"(c[3])
        : "r"(a[0]), "r"(a[1]), "r"(a[2]), "r"(a[3]), "r"(b[0]), "r"(b[1]));
}

// ---------------- grouped expert GEMM (bf16x3 compensated) ----------------
// PHASE 1: H[off+row, :] = gelu( X[tok[row], :] @ W1[e] + b1[e] )   (K=1024, N=4096)
// PHASE 2: slot[tok,k,:]  =       H[off+row, :] @ W2[e] + b2[e]     (K=4096, N=1024)
template <int PHASE>
__global__ void __launch_bounds__(256) moe_gemm(const float* __restrict__ X,
                                                const float* __restrict__ W,
                                                const float* __restrict__ BiasAll) {
    constexpr int K = (PHASE == 1) ? EMBED : HIDDEN;
    constexpr int N = (PHASE == 1) ? HIDDEN : EMBED;
    constexpr int BM = 128, BN = 128, BK = 32;
    constexpr int LDA = BK + 8;   // 40: conflict-free float2 A-fragment LDS
    constexpr int LDB = BN + 4;   // 132: conflict-free B-fragment LDS (rows 2tg,2tg+1)
    extern __shared__ float smem[];
    float* sA = smem;                   // 2 stages of [BM][LDA]
    float* sB = smem + 2 * BM * LDA;    // 2 stages of [BK][LDB]
    __shared__ const float* rowptr[BM];

    const int e = blockIdx.z;
    const int cnt = g_count[e];
    const int m0 = blockIdx.y * BM;
    if (m0 >= cnt) return;
    const int n0 = blockIdx.x * BN;
    const int off = g_offset[e];
    const float* Wb = W + (size_t)e * K * N;
    const float* bias = BiasAll + (size_t)e * N;
    const int tid = threadIdx.x;

    for (int r = tid; r < BM; r += 256) {
        int row = m0 + r;
        const float* p = nullptr;
        if (row < cnt) {
            if (PHASE == 1) p = X + (size_t)g_tok[e * MAXROWS + row] * EMBED;
            else            p = g_h + (size_t)(off + row) * HIDDEN;
        }
        rowptr[r] = p;
    }
    __syncthreads();

    auto loadA = [&](int stage, int kt) {
        float* dst = sA + stage * (BM * LDA);
        const int k0 = kt * BK;
#pragma unroll
        for (int i = 0; i < 4; i++) {
            int chunk = tid + i * 256;       // 1024 16B-chunks: 128 rows x 8
            int r = chunk >> 3;
            int c = (chunk & 7) << 2;
            const float* p = rowptr[r];
            cp16(dst + r * LDA + c, p ? (const void*)(p + k0 + c) : (const void*)Wb, p != nullptr);
        }
    };
    auto loadB = [&](int stage, int kt) {
        float* dst = sB + stage * (BK * LDB);
        const int k0 = kt * BK;
#pragma unroll
        for (int i = 0; i < 4; i++) {
            int chunk = tid + i * 256;       // 1024 chunks: 32 k-rows x 32
            int kk = chunk >> 5;
            int c = (chunk & 31) << 2;
            cp16(dst + kk * LDB + c, (const void*)(Wb + (size_t)(k0 + kk) * N + n0 + c), true);
        }
    };

    float acc[4][4][4];
#pragma unroll
    for (int mi = 0; mi < 4; mi++)
#pragma unroll
        for (int ni = 0; ni < 4; ni++)
#pragma unroll
            for (int q = 0; q < 4; q++) acc[mi][ni][q] = 0.f;

    const int wid = tid >> 5;
    const int lane = tid & 31;
    const int wm = (wid & 1) * 64;       // 2 warps along M
    const int wn = (wid >> 1) * 32;      // 4 warps along N
    const int g = lane >> 2;             // groupID
    const int tg = lane & 3;             // threadID_in_group

    constexpr int KT = K / BK;
    loadA(0, 0); loadB(0, 0);
    asm volatile("cp.async.commit_group;\n");

    for (int kt = 0; kt < KT; kt++) {
        if (kt + 1 < KT) {
            loadA((kt + 1) & 1, kt + 1);
            loadB((kt + 1) & 1, kt + 1);
            asm volatile("cp.async.commit_group;\n");
            asm volatile("cp.async.wait_group 1;\n");
        } else {
            asm volatile("cp.async.wait_group 0;\n");
        }
        __syncthreads();
        const float* A = sA + (kt & 1) * (BM * LDA);
        const float* B = sB + (kt & 1) * (BK * LDB);
#pragma unroll
        for (int ks = 0; ks < BK / 16; ks++) {
            uint32_t ah[4][4], al[4][4];
            uint32_t bh[4][2], bl[4][2];
#pragma unroll
            for (int mi = 0; mi < 4; mi++) {
                const float* ap = A + (wm + mi * 16 + g) * LDA + ks * 16 + 2 * tg;
                float2 v00 = *reinterpret_cast<const float2*>(ap);            // row g,   k 2tg..
                float2 v10 = *reinterpret_cast<const float2*>(ap + 8 * LDA);  // row g+8
                float2 v01 = *reinterpret_cast<const float2*>(ap + 8);        // row g,   k 2tg+8..
                float2 v11 = *reinterpret_cast<const float2*>(ap + 8 * LDA + 8);
                split2(v00.x, v00.y, ah[mi][0], al[mi][0]);
                split2(v10.x, v10.y, ah[mi][1], al[mi][1]);
                split2(v01.x, v01.y, ah[mi][2], al[mi][2]);
                split2(v11.x, v11.y, ah[mi][3], al[mi][3]);
            }
#pragma unroll
            for (int ni = 0; ni < 4; ni++) {
                const float* bp = B + (ks * 16 + 2 * tg) * LDB + wn + ni * 8 + g;
                float x0 = bp[0];            // k = 2tg
                float x1 = bp[LDB];          // k = 2tg+1
                float x2 = bp[8 * LDB];      // k = 2tg+8
                float x3 = bp[9 * LDB];      // k = 2tg+9
                split2(x0, x1, bh[ni][0], bl[ni][0]);
                split2(x2, x3, bh[ni][1], bl[ni][1]);
            }
#pragma unroll
            for (int mi = 0; mi < 4; mi++)
#pragma unroll
                for (int ni = 0; ni < 4; ni++) {
                    mma_bf16(acc[mi][ni], ah[mi], bh[ni]);   // hi*hi
                    mma_bf16(acc[mi][ni], ah[mi], bl[ni]);   // hi*lo
                    mma_bf16(acc[mi][ni], al[mi], bh[ni]);   // lo*hi
                }
        }
        __syncthreads();
    }

    // epilogue (m16n8k16 C layout == m16n8k8: rows g/g+8, cols 2tg,2tg+1)
#pragma unroll
    for (int mi = 0; mi < 4; mi++) {
#pragma unroll
        for (int rr = 0; rr < 2; rr++) {
            int rloc = wm + mi * 16 + g + rr * 8;
            int row = m0 + rloc;
            if (row >= cnt) continue;
            if (PHASE == 1) {
                float* outp = g_h + (size_t)(off + row) * HIDDEN + n0;
#pragma unroll
                for (int ni = 0; ni < 4; ni++) {
                    int col = wn + ni * 8 + 2 * tg;
                    float v0 = acc[mi][ni][rr * 2 + 0] + bias[n0 + col];
                    float v1 = acc[mi][ni][rr * 2 + 1] + bias[n0 + col + 1];
                    outp[col]     = gelu_exact(v0);
                    outp[col + 1] = gelu_exact(v1);
                }
            } else {
                int t  = g_tok[e * MAXROWS + row];
                int kk = g_kslot[e * MAXROWS + row];
                float* outp = g_slot + ((size_t)t * 2 + kk) * EMBED + n0;
#pragma unroll
                for (int ni = 0; ni < 4; ni++) {
                    int col = wn + ni * 8 + 2 * tg;
                    outp[col]     = acc[mi][ni][rr * 2 + 0] + bias[n0 + col];
                    outp[col + 1] = acc[mi][ni][rr * 2 + 1] + bias[n0 + col + 1];
                }
            }
        }
    }
}

__global__ void combine_kernel(float* __restrict__ out) {
    int t = blockIdx.x;
    int i = threadIdx.x;  // 256 threads, one float4 each (EMBED/4 = 256)
    float w0 = g_topw[t * 2 + 0], w1 = g_topw[t * 2 + 1];
    const float4* s0 = reinterpret_cast<const float4*>(g_slot + (size_t)t * 2 * EMBED);
    const float4* s1 = reinterpret_cast<const float4*>(g_slot + ((size_t)t * 2 + 1) * EMBED);
    float4 a = s0[i], b = s1[i];
    float4 r;
    r.x = w0 * a.x + w1 * b.x;
    r.y = w0 * a.y + w1 * b.y;
    r.z = w0 * a.z + w1 * b.z;
    r.w = w0 * a.w + w1 * b.w;
    reinterpret_cast<float4*>(out + (size_t)t * EMBED)[i] = r;
}

// ---------------- launch ----------------
extern "C" void kernel_launch(void* const* d_in, const int* in_sizes, int n_in,
                              void* d_out, int out_size) {
    const float* x   = (const float*)d_in[0];
    const float* gw  = (const float*)d_in[1];
    const float* w1  = (const float*)d_in[2];
    const float* b1  = (const float*)d_in[3];
    const float* w2  = (const float*)d_in[4];
    const float* b2  = (const float*)d_in[5];
    float* out = (float*)d_out;

    constexpr int SMEM_BYTES = 2 * (128 * 40 + 32 * 132) * 4;  // 74752 B
    cudaFuncSetAttribute(moe_gemm<1>, cudaFuncAttributeMaxDynamicSharedMemorySize, SMEM_BYTES);
    cudaFuncSetAttribute(moe_gemm<2>, cudaFuncAttributeMaxDynamicSharedMemorySize, SMEM_BYTES);

    init_kernel<<<1, 32>>>();
    router_kernel<<<NTOK / 8, 256>>>(x, gw);   // 8 warps/block, 1 warp/token
    offsets_kernel<<<1, 32>>>();

    dim3 grid1(HIDDEN / 128, MAXROWS / 128, NEXP);  // (32, 16, 8), most y-tiles early-exit
    moe_gemm<1><<<grid1, 256, SMEM_BYTES>>>(x, w1, b1);

    dim3 grid2(EMBED / 128, MAXROWS / 128, NEXP);   // (8, 16, 8)
    moe_gemm<2><<<grid2, 256, SMEM_BYTES>>>(x, w2, b2);

    combine_kernel<<<NTOK, 256>>>(out);
}

// round 3
// speedup vs baseline: 1.2301x; 1.2301x over previous
#include <cuda_runtime.h>
#include <cuda_bf16.h>
#include <cstdint>
#include <math.h>

#define EMBED 1024
#define HIDDEN 4096
#define NEXP 8
#define NTOK 1024
#define MAXROWS 2048   // NTOK * TOP_K

// ---------------- device scratch ----------------
__device__ float g_h[MAXROWS * HIDDEN];          // 32 MB: gelu(x@w1+b1), compacted rows
__device__ float g_slot[NTOK * 2 * EMBED];       // 8 MB: per (token, k) expert output
__device__ float g_topw[NTOK * 2];               // renormalized top-2 gate weights
__device__ int   g_tok[NEXP * MAXROWS];          // per-expert gathered token ids
__device__ int   g_kslot[NEXP * MAXROWS];        // which of the 2 slots this row fills
__device__ int   g_count[NEXP];
__device__ int   g_offset[NEXP];

// ---------------- small kernels ----------------
__global__ void init_kernel() {
    if (threadIdx.x < NEXP) g_count[threadIdx.x] = 0;
}

__global__ void router_kernel(const float* __restrict__ x, const float* __restrict__ gw) {
    int warp = (blockIdx.x * blockDim.x + threadIdx.x) >> 5;
    int lane = threadIdx.x & 31;
    if (warp >= NTOK) return;
    const float* xr = x + (size_t)warp * EMBED;
    float acc[NEXP];
#pragma unroll
    for (int n = 0; n < NEXP; n++) acc[n] = 0.f;
    for (int d = lane; d < EMBED; d += 32) {
        float xv = xr[d];
#pragma unroll
        for (int n = 0; n < NEXP; n++) acc[n] += xv * gw[n * EMBED + d];
    }
#pragma unroll
    for (int n = 0; n < NEXP; n++)
#pragma unroll
        for (int o = 16; o > 0; o >>= 1) acc[n] += __shfl_xor_sync(0xffffffffu, acc[n], o);
    if (lane == 0) {
        float mx = acc[0];
#pragma unroll
        for (int n = 1; n < NEXP; n++) mx = fmaxf(mx, acc[n]);
        float p[NEXP], s = 0.f;
#pragma unroll
        for (int n = 0; n < NEXP; n++) { p[n] = expf(acc[n] - mx); s += p[n]; }
        float inv = 1.f / s;
#pragma unroll
        for (int n = 0; n < NEXP; n++) p[n] *= inv;
        int i0 = 0;
#pragma unroll
        for (int n = 1; n < NEXP; n++) if (p[n] > p[i0]) i0 = n;
        int i1 = (i0 == 0) ? 1 : 0;
#pragma unroll
        for (int n = 0; n < NEXP; n++) if (n != i0 && p[n] > p[i1]) i1 = n;
        float w0 = p[i0], w1 = p[i1];
        float rs = 1.f / (w0 + w1 + 1e-9f);
        g_topw[warp * 2 + 0] = w0 * rs;
        g_topw[warp * 2 + 1] = w1 * rs;
        int pos0 = atomicAdd(&g_count[i0], 1);
        g_tok[i0 * MAXROWS + pos0] = warp; g_kslot[i0 * MAXROWS + pos0] = 0;
        int pos1 = atomicAdd(&g_count[i1], 1);
        g_tok[i1 * MAXROWS + pos1] = warp; g_kslot[i1 * MAXROWS + pos1] = 1;
    }
}

__global__ void offsets_kernel() {
    if (threadIdx.x == 0) {
        int o = 0;
        for (int e = 0; e < NEXP; e++) { g_offset[e] = o; o += g_count[e]; }
    }
}

// ---------------- helpers ----------------
__device__ __forceinline__ float gelu_exact(float v) {
    return 0.5f * v * (1.0f + erff(v * 0.7071067811865476f));
}

// split two fp32 into packed bf16x2 (hi) + packed bf16x2 (lo residual)
__device__ __forceinline__ void split2(float x, float y, uint32_t& hi, uint32_t& lo) {
    __nv_bfloat162 h = __floats2bfloat162_rn(x, y);   // .x (low half) = x
    float rx = x - __bfloat162float(h.x);
    float ry = y - __bfloat162float(h.y);
    __nv_bfloat162 l = __floats2bfloat162_rn(rx, ry);
    hi = *reinterpret_cast<uint32_t*>(&h);
    lo = *reinterpret_cast<uint32_t*>(&l);
}

__device__ __forceinline__ void mma_bf16(float c[4], const uint32_t a[4], const uint32_t b0, const uint32_t b1) {
    asm volatile(
        "mma.sync.aligned.m16n8k16.row.col.f32.bf16.bf16.f32 "
        "{%0,%1,%2,%3}, {%4,%5,%6,%7}, {%8,%9}, {%0,%1,%2,%3};\n"
        : "+f"(c[0]), "+f"(c[1]), "+f"(c[2]), "+f"(c[3])
        : "r"(a[0]), "r"(a[1]), "r"(a[2]), "r"(a[3]), "r"(b0), "r"(b1));
}

__device__ __forceinline__ void ldsm_x4(uint32_t& r0, uint32_t& r1, uint32_t& r2, uint32_t& r3, uint32_t addr) {
    asm volatile("ldmatrix.sync.aligned.m8n8.x4.shared.b16 {%0,%1,%2,%3}, [%4];\n"
                 : "=r"(r0), "=r"(r1), "=r"(r2), "=r"(r3) : "r"(addr));
}

__device__ __forceinline__ void ldsm_x4_t(uint32_t& r0, uint32_t& r1, uint32_t& r2, uint32_t& r3, uint32_t addr) {
    asm volatile("ldmatrix.sync.aligned.m8n8.x4.trans.shared.b16 {%0,%1,%2,%3}, [%4];\n"
                 : "=r"(r0), "=r"(r1), "=r"(r2), "=r"(r3) : "r"(addr));
}

// ---------------- grouped expert GEMM (bf16x3, split-at-STS, ldmatrix) ----------------
// PHASE 1: H[off+row, :] = gelu( X[tok[row], :] @ W1[e] + b1[e] )   (K=1024, N=4096)
// PHASE 2: slot[tok,k,:]  =       H[off+row, :] @ W2[e] + b2[e]     (K=4096, N=1024)
template <int PHASE>
__global__ void __launch_bounds__(256) moe_gemm(const float* __restrict__ X,
                                                const float* __restrict__ W,
                                                const float* __restrict__ BiasAll) {
    constexpr int K = (PHASE == 1) ? EMBED : HIDDEN;
    constexpr int N = (PHASE == 1) ? HIDDEN : EMBED;
    constexpr int BM = 128, BN = 128, BK = 32;
    constexpr int LDA = BK + 8;    // 40 bf16 = 80B row stride: ldmatrix conflict-free
    constexpr int LDB = BN + 8;    // 136 bf16 = 272B row stride: ldmatrix conflict-free
    constexpr int A_STAGE = BM * LDA;   // 5120 bf16
    constexpr int B_STAGE = BK * LDB;   // 4352 bf16

    extern __shared__ __nv_bfloat16 smem[];
    __nv_bfloat16* sAh = smem;                          // [2][A_STAGE]
    __nv_bfloat16* sAl = smem + 2 * A_STAGE;            // [2][A_STAGE]
    __nv_bfloat16* sBh = smem + 4 * A_STAGE;            // [2][B_STAGE]
    __nv_bfloat16* sBl = smem + 4 * A_STAGE + 2 * B_STAGE;
    __shared__ const float* rowptr[BM];

    const int e = blockIdx.z;
    const int cnt = g_count[e];
    const int m0 = blockIdx.y * BM;
    if (m0 >= cnt) return;
    const int n0 = blockIdx.x * BN;
    const int off = g_offset[e];
    const float* Wb = W + (size_t)e * K * N;
    const float* bias = BiasAll + (size_t)e * N;
    const int tid = threadIdx.x;

    for (int r = tid; r < BM; r += 256) {
        int row = m0 + r;
        const float* p = nullptr;
        if (row < cnt) {
            if (PHASE == 1) p = X + (size_t)g_tok[e * MAXROWS + row] * EMBED;
            else            p = g_h + (size_t)(off + row) * HIDDEN;
        }
        rowptr[r] = p;
    }
    __syncthreads();

    // register staging for global loads (double-buffered via loop structure)
    float ra[16], rb[16];

    auto ldgA = [&](int kt) {
        const int k0 = kt * BK;
#pragma unroll
        for (int i = 0; i < 4; i++) {
            int chunk = tid + i * 256;          // 1024 chunks: 128 rows x 8 float4
            int r = chunk >> 3;
            int c = (chunk & 7) << 2;
            const float* p = rowptr[r];
            float4 v = p ? *reinterpret_cast<const float4*>(p + k0 + c)
                         : make_float4(0.f, 0.f, 0.f, 0.f);
            ra[4 * i + 0] = v.x; ra[4 * i + 1] = v.y; ra[4 * i + 2] = v.z; ra[4 * i + 3] = v.w;
        }
    };
    auto ldgB = [&](int kt) {
        const int k0 = kt * BK;
#pragma unroll
        for (int i = 0; i < 4; i++) {
            int chunk = tid + i * 256;          // 1024 chunks: 32 k-rows x 32 float4
            int kk = chunk >> 5;
            int c = (chunk & 31) << 2;
            float4 v = *reinterpret_cast<const float4*>(Wb + (size_t)(k0 + kk) * N + n0 + c);
            rb[4 * i + 0] = v.x; rb[4 * i + 1] = v.y; rb[4 * i + 2] = v.z; rb[4 * i + 3] = v.w;
        }
    };
    auto stsA = [&](int stage) {
        __nv_bfloat16* dh = sAh + stage * A_STAGE;
        __nv_bfloat16* dl = sAl + stage * A_STAGE;
#pragma unroll
        for (int i = 0; i < 4; i++) {
            int chunk = tid + i * 256;
            int r = chunk >> 3;
            int c = (chunk & 7) << 2;
            uint2 h, l;
            split2(ra[4 * i + 0], ra[4 * i + 1], h.x, l.x);
            split2(ra[4 * i + 2], ra[4 * i + 3], h.y, l.y);
            *reinterpret_cast<uint2*>(dh + r * LDA + c) = h;
            *reinterpret_cast<uint2*>(dl + r * LDA + c) = l;
        }
    };
    auto stsB = [&](int stage) {
        __nv_bfloat16* dh = sBh + stage * B_STAGE;
        __nv_bfloat16* dl = sBl + stage * B_STAGE;
#pragma unroll
        for (int i = 0; i < 4; i++) {
            int chunk = tid + i * 256;
            int kk = chunk >> 5;
            int c = (chunk & 31) << 2;
            uint2 h, l;
            split2(rb[4 * i + 0], rb[4 * i + 1], h.x, l.x);
            split2(rb[4 * i + 2], rb[4 * i + 3], h.y, l.y);
            *reinterpret_cast<uint2*>(dh + kk * LDB + c) = h;
            *reinterpret_cast<uint2*>(dl + kk * LDB + c) = l;
        }
    };

    float acc[4][4][4];
#pragma unroll
    for (int mi = 0; mi < 4; mi++)
#pragma unroll
        for (int ni = 0; ni < 4; ni++)
#pragma unroll
            for (int q = 0; q < 4; q++) acc[mi][ni][q] = 0.f;

    const int wid = tid >> 5;
    const int lane = tid & 31;
    const int wm = (wid & 1) * 64;       // 2 warps along M
    const int wn = (wid >> 1) * 32;      // 4 warps along N
    const int g = lane >> 2;             // groupID
    const int tg = lane & 3;             // threadID_in_group

    // per-lane ldmatrix row/col components (16B-granule addresses)
    const int aRow = (lane & 15);            // + wm + mi*16
    const int aColOff = (lane >> 4) << 3;    // 0 or 8 (k offset)
    const int bKrow = (lane & 15);           // + ks*16
    const int bColOff = (lane >> 4) << 3;    // 0 or 8 (n offset)

    const uint32_t sAh_u = (uint32_t)__cvta_generic_to_shared(sAh);
    const uint32_t sAl_u = (uint32_t)__cvta_generic_to_shared(sAl);
    const uint32_t sBh_u = (uint32_t)__cvta_generic_to_shared(sBh);
    const uint32_t sBl_u = (uint32_t)__cvta_generic_to_shared(sBl);

    constexpr int KT = K / BK;
    ldgA(0); ldgB(0);
    stsA(0); stsB(0);
    __syncthreads();

    for (int kt = 0; kt < KT; kt++) {
        if (kt + 1 < KT) { ldgA(kt + 1); ldgB(kt + 1); }

        const int st = kt & 1;
        const uint32_t aBaseH = sAh_u + (uint32_t)(st * A_STAGE) * 2u;
        const uint32_t aBaseL = sAl_u + (uint32_t)(st * A_STAGE) * 2u;
        const uint32_t bBaseH = sBh_u + (uint32_t)(st * B_STAGE) * 2u;
        const uint32_t bBaseL = sBl_u + (uint32_t)(st * B_STAGE) * 2u;

#pragma unroll
        for (int ks = 0; ks < BK / 16; ks++) {
            uint32_t ah[4][4], al[4][4];
            uint32_t bh[4][2], bl[4][2];
            // A fragments: x4 per 16-row block
#pragma unroll
            for (int mi = 0; mi < 4; mi++) {
                uint32_t addr = aBaseH + ((uint32_t)((wm + mi * 16 + aRow) * LDA + ks * 16 + aColOff) << 1);
                ldsm_x4(ah[mi][0], ah[mi][1], ah[mi][2], ah[mi][3], addr);
                uint32_t addrl = aBaseL + ((uint32_t)((wm + mi * 16 + aRow) * LDA + ks * 16 + aColOff) << 1);
                ldsm_x4(al[mi][0], al[mi][1], al[mi][2], al[mi][3], addrl);
            }
            // B fragments: x4.trans covers two ni blocks (n width 16) each
#pragma unroll
            for (int nj = 0; nj < 2; nj++) {
                uint32_t boff = (uint32_t)((ks * 16 + bKrow) * LDB + wn + nj * 16 + bColOff) << 1;
                ldsm_x4_t(bh[2 * nj][0], bh[2 * nj][1], bh[2 * nj + 1][0], bh[2 * nj + 1][1], bBaseH + boff);
                ldsm_x4_t(bl[2 * nj][0], bl[2 * nj][1], bl[2 * nj + 1][0], bl[2 * nj + 1][1], bBaseL + boff);
            }
#pragma unroll
            for (int mi = 0; mi < 4; mi++)
#pragma unroll
                for (int ni = 0; ni < 4; ni++) {
                    mma_bf16(acc[mi][ni], ah[mi], bh[ni][0], bh[ni][1]);   // hi*hi
                    mma_bf16(acc[mi][ni], ah[mi], bl[ni][0], bl[ni][1]);   // hi*lo
                    mma_bf16(acc[mi][ni], al[mi], bh[ni][0], bh[ni][1]);   // lo*hi
                }
        }

        if (kt + 1 < KT) { stsA((kt + 1) & 1); stsB((kt + 1) & 1); }
        __syncthreads();
    }

    // epilogue (C layout: rows g/g+8, cols 2tg,2tg+1)
#pragma unroll
    for (int mi = 0; mi < 4; mi++) {
#pragma unroll
        for (int rr = 0; rr < 2; rr++) {
            int rloc = wm + mi * 16 + g + rr * 8;
            int row = m0 + rloc;
            if (row >= cnt) continue;
            if (PHASE == 1) {
                float* outp = g_h + (size_t)(off + row) * HIDDEN + n0;
#pragma unroll
                for (int ni = 0; ni < 4; ni++) {
                    int col = wn + ni * 8 + 2 * tg;
                    float v0 = acc[mi][ni][rr * 2 + 0] + bias[n0 + col];
                    float v1 = acc[mi][ni][rr * 2 + 1] + bias[n0 + col + 1];
                    outp[col]     = gelu_exact(v0);
                    outp[col + 1] = gelu_exact(v1);
                }
            } else {
                int t  = g_tok[e * MAXROWS + row];
                int kk = g_kslot[e * MAXROWS + row];
                float* outp = g_slot + ((size_t)t * 2 + kk) * EMBED + n0;
#pragma unroll
                for (int ni = 0; ni < 4; ni++) {
                    int col = wn + ni * 8 + 2 * tg;
                    outp[col]     = acc[mi][ni][rr * 2 + 0] + bias[n0 + col];
                    outp[col + 1] = acc[mi][ni][rr * 2 + 1] + bias[n0 + col + 1];
                }
            }
        }
    }
}

__global__ void combine_kernel(float* __restrict__ out) {
    int t = blockIdx.x;
    int i = threadIdx.x;  // 256 threads, one float4 each (EMBED/4 = 256)
    float w0 = g_topw[t * 2 + 0], w1 = g_topw[t * 2 + 1];
    const float4* s0 = reinterpret_cast<const float4*>(g_slot + (size_t)t * 2 * EMBED);
    const float4* s1 = reinterpret_cast<const float4*>(g_slot + ((size_t)t * 2 + 1) * EMBED);
    float4 a = s0[i], b = s1[i];
    float4 r;
    r.x = w0 * a.x + w1 * b.x;
    r.y = w0 * a.y + w1 * b.y;
    r.z = w0 * a.z + w1 * b.z;
    r.w = w0 * a.w + w1 * b.w;
    reinterpret_cast<float4*>(out + (size_t)t * EMBED)[i] = r;
}

// ---------------- launch ----------------
extern "C" void kernel_launch(void* const* d_in, const int* in_sizes, int n_in,
                              void* d_out, int out_size) {
    const float* x   = (const float*)d_in[0];
    const float* gw  = (const float*)d_in[1];
    const float* w1  = (const float*)d_in[2];
    const float* b1  = (const float*)d_in[3];
    const float* w2  = (const float*)d_in[4];
    const float* b2  = (const float*)d_in[5];
    float* out = (float*)d_out;

    // smem: 2 stages x (A hi+lo 128x40 + B hi+lo 32x136) bf16
    constexpr int SMEM_BYTES = (4 * 128 * 40 + 4 * 32 * 136) * 2;  // 75776 B
    cudaFuncSetAttribute(moe_gemm<1>, cudaFuncAttributeMaxDynamicSharedMemorySize, SMEM_BYTES);
    cudaFuncSetAttribute(moe_gemm<2>, cudaFuncAttributeMaxDynamicSharedMemorySize, SMEM_BYTES);

    init_kernel<<<1, 32>>>();
    router_kernel<<<NTOK / 8, 256>>>(x, gw);   // 8 warps/block, 1 warp/token
    offsets_kernel<<<1, 32>>>();

    dim3 grid1(HIDDEN / 128, MAXROWS / 128, NEXP);  // (32, 16, 8), most y-tiles early-exit
    moe_gemm<1><<<grid1, 256, SMEM_BYTES>>>(x, w1, b1);

    dim3 grid2(EMBED / 128, MAXROWS / 128, NEXP);   // (8, 16, 8)
    moe_gemm<2><<<grid2, 256, SMEM_BYTES>>>(x, w2, b2);

    combine_kernel<<<NTOK, 256>>>(out);
}

// round 5
// speedup vs baseline: 1.3918x; 1.1314x over previous
#include <cuda_runtime.h>
#include <cuda_bf16.h>
#include <cstdint>
#include <math.h>

#define EMBED 1024
#define HIDDEN 4096
#define NEXP 8
#define NTOK 1024
#define MAXROWS 2048   // NTOK * TOP_K

// ---------------- device scratch ----------------
// H scratch stored as bf16 hi/lo, row-major, padded by 128 rows (phase-2 tiles overhang)
__device__ __nv_bfloat16 g_hh[(MAXROWS + 128) * HIDDEN];
__device__ __nv_bfloat16 g_hl[(MAXROWS + 128) * HIDDEN];
__device__ float g_slot[NTOK * 2 * EMBED];
__device__ float g_topw[NTOK * 2];
__device__ int   g_tok[NEXP * MAXROWS];
__device__ int   g_kslot[NEXP * MAXROWS];
__device__ int   g_count[NEXP];
__device__ int   g_offset[NEXP];

// ---------------- small kernels ----------------
__global__ void init_kernel() {
    if (threadIdx.x < NEXP) g_count[threadIdx.x] = 0;
}

__global__ void router_kernel(const float* __restrict__ x, const float* __restrict__ gw) {
    int warp = (blockIdx.x * blockDim.x + threadIdx.x) >> 5;
    int lane = threadIdx.x & 31;
    if (warp >= NTOK) return;
    const float* xr = x + (size_t)warp * EMBED;
    float acc[NEXP];
#pragma unroll
    for (int n = 0; n < NEXP; n++) acc[n] = 0.f;
    for (int d = lane; d < EMBED; d += 32) {
        float xv = xr[d];
#pragma unroll
        for (int n = 0; n < NEXP; n++) acc[n] += xv * gw[n * EMBED + d];
    }
#pragma unroll
    for (int n = 0; n < NEXP; n++)
#pragma unroll
        for (int o = 16; o > 0; o >>= 1) acc[n] += __shfl_xor_sync(0xffffffffu, acc[n], o);
    if (lane == 0) {
        float mx = acc[0];
#pragma unroll
        for (int n = 1; n < NEXP; n++) mx = fmaxf(mx, acc[n]);
        float p[NEXP], s = 0.f;
#pragma unroll
        for (int n = 0; n < NEXP; n++) { p[n] = expf(acc[n] - mx); s += p[n]; }
        float inv = 1.f / s;
#pragma unroll
        for (int n = 0; n < NEXP; n++) p[n] *= inv;
        int i0 = 0;
#pragma unroll
        for (int n = 1; n < NEXP; n++) if (p[n] > p[i0]) i0 = n;
        int i1 = (i0 == 0) ? 1 : 0;
#pragma unroll
        for (int n = 0; n < NEXP; n++) if (n != i0 && p[n] > p[i1]) i1 = n;
        float w0 = p[i0], w1 = p[i1];
        float rs = 1.f / (w0 + w1 + 1e-9f);
        g_topw[warp * 2 + 0] = w0 * rs;
        g_topw[warp * 2 + 1] = w1 * rs;
        int pos0 = atomicAdd(&g_count[i0], 1);
        g_tok[i0 * MAXROWS + pos0] = warp; g_kslot[i0 * MAXROWS + pos0] = 0;
        int pos1 = atomicAdd(&g_count[i1], 1);
        g_tok[i1 * MAXROWS + pos1] = warp; g_kslot[i1 * MAXROWS + pos1] = 1;
    }
}

__global__ void offsets_kernel() {
    if (threadIdx.x == 0) {
        int o = 0;
        for (int e = 0; e < NEXP; e++) { g_offset[e] = o; o += g_count[e]; }
    }
}

// ---------------- helpers ----------------
__device__ __forceinline__ float gelu_exact(float v) {
    return 0.5f * v * (1.0f + erff(v * 0.7071067811865476f));
}

__device__ __forceinline__ void split2(float x, float y, uint32_t& hi, uint32_t& lo) {
    __nv_bfloat162 h = __floats2bfloat162_rn(x, y);   // .x (low half) = x
    float rx = x - __bfloat162float(h.x);
    float ry = y - __bfloat162float(h.y);
    __nv_bfloat162 l = __floats2bfloat162_rn(rx, ry);
    hi = *reinterpret_cast<uint32_t*>(&h);
    lo = *reinterpret_cast<uint32_t*>(&l);
}

__device__ __forceinline__ void cp16(void* dst_smem, const void* src) {
    uint32_t d = (uint32_t)__cvta_generic_to_shared(dst_smem);
    asm volatile("cp.async.cg.shared.global [%0], [%1], 16;\n" ::"r"(d), "l"(src));
}

__device__ __forceinline__ void mma_bf16(float c[4], const uint32_t a[4], const uint32_t b0, const uint32_t b1) {
    asm volatile(
        "mma.sync.aligned.m16n8k16.row.col.f32.bf16.bf16.f32 "
        "{%0,%1,%2,%3}, {%4,%5,%6,%7}, {%8,%9}, {%0,%1,%2,%3};\n"
        : "+f"(c[0]), "+f"(c[1]), "+f"(c[2]), "+f"(c[3])
        : "r"(a[0]), "r"(a[1]), "r"(a[2]), "r"(a[3]), "r"(b0), "r"(b1));
}

__device__ __forceinline__ void ldsm_x4(uint32_t& r0, uint32_t& r1, uint32_t& r2, uint32_t& r3, uint32_t addr) {
    asm volatile("ldmatrix.sync.aligned.m8n8.x4.shared.b16 {%0,%1,%2,%3}, [%4];\n"
                 : "=r"(r0), "=r"(r1), "=r"(r2), "=r"(r3) : "r"(addr));
}

__device__ __forceinline__ void ldsm_x4_t(uint32_t& r0, uint32_t& r1, uint32_t& r2, uint32_t& r3, uint32_t addr) {
    asm volatile("ldmatrix.sync.aligned.m8n8.x4.trans.shared.b16 {%0,%1,%2,%3}, [%4];\n"
                 : "=r"(r0), "=r"(r1), "=r"(r2), "=r"(r3) : "r"(addr));
}

// ---------------- grouped expert GEMM (bf16x3, 2 CTAs/SM) ----------------
// PHASE 1: Hhi/Hlo[off+row,:] = split(gelu( X[tok[row],:] @ W1[e] + b1[e] ))  K=1024, N=4096
// PHASE 2: slot[tok,k,:]       =        H[off+row,:] @ W2[e] + b2[e]          K=4096, N=1024
template <int PHASE>
__global__ void __launch_bounds__(256, 2) moe_gemm(const float* __restrict__ X,
                                                   const float* __restrict__ W,
                                                   const float* __restrict__ BiasAll) {
    constexpr int K = (PHASE == 1) ? EMBED : HIDDEN;
    constexpr int N = (PHASE == 1) ? HIDDEN : EMBED;
    constexpr int BM = 128, BN = 128, BK = 32;
    constexpr int LDA = BK + 8;    // 40 bf16 (80B): ldmatrix + cp.async/STS conflict-free
    constexpr int LDB = BN + 8;    // 136 bf16 (272B)
    constexpr int A_STAGE = BM * LDA;   // 5120 bf16
    constexpr int B_STAGE = BK * LDB;   // 4352 bf16

    extern __shared__ __nv_bfloat16 smem[];
    __nv_bfloat16* sAh = smem;
    __nv_bfloat16* sAl = smem + 2 * A_STAGE;
    __nv_bfloat16* sBh = smem + 4 * A_STAGE;
    __nv_bfloat16* sBl = smem + 4 * A_STAGE + 2 * B_STAGE;
    __shared__ const float* rowptr[BM];

    const int e = blockIdx.z;
    const int cnt = g_count[e];
    const int m0 = blockIdx.y * BM;
    if (m0 >= cnt) return;
    const int n0 = blockIdx.x * BN;
    const int off = g_offset[e];
    const float* Wb = W + (size_t)e * K * N;
    const float* bias = BiasAll + (size_t)e * N;
    const int tid = threadIdx.x;

    if (PHASE == 1) {
        for (int r = tid; r < BM; r += 256) {
            int row = m0 + r;
            rowptr[r] = (row < cnt) ? (X + (size_t)g_tok[e * MAXROWS + row] * EMBED) : nullptr;
        }
        __syncthreads();
    }

    float ra[8], rb[8];   // half-tile staging

    // ---- A path ----
    // phase 1: ldg fp32 + split + sts, in two k16 halves
    auto ldgA = [&](int kt, int h) {
#pragma unroll
        for (int i = 0; i < 2; i++) {
            int chunk = tid + i * 256;       // 512 chunks: 128 rows x 4 float4 (16 k)
            int r = chunk >> 2;
            int cc = (chunk & 3) << 2;
            const float* p = rowptr[r];
            float4 v = make_float4(0.f, 0.f, 0.f, 0.f);
            if (p) v = *reinterpret_cast<const float4*>(p + kt * BK + h * 16 + cc);
            ra[4 * i + 0] = v.x; ra[4 * i + 1] = v.y; ra[4 * i + 2] = v.z; ra[4 * i + 3] = v.w;
        }
    };
    auto stsA = [&](int st, int h) {
        __nv_bfloat16* dh = sAh + st * A_STAGE;
        __nv_bfloat16* dl = sAl + st * A_STAGE;
#pragma unroll
        for (int i = 0; i < 2; i++) {
            int chunk = tid + i * 256;
            int r = chunk >> 2;
            int cc = (chunk & 3) << 2;
            uint2 hv, lv;
            split2(ra[4 * i + 0], ra[4 * i + 1], hv.x, lv.x);
            split2(ra[4 * i + 2], ra[4 * i + 3], hv.y, lv.y);
            *reinterpret_cast<uint2*>(dh + r * LDA + h * 16 + cc) = hv;
            *reinterpret_cast<uint2*>(dl + r * LDA + h * 16 + cc) = lv;
        }
    };
    // phase 2: raw cp.async of pre-split bf16 H rows (full tile at once, no regs)
    auto cpA = [&](int st, int kt) {
#pragma unroll
        for (int i = 0; i < 4; i++) {
            int chunk = tid + i * 256;       // 1024 chunks: hi 512 + lo 512
            int sel = chunk >> 9;
            int c2 = chunk & 511;
            int r = c2 >> 2;
            int cc = (c2 & 3) << 3;          // bf16 col: 0,8,16,24
            const __nv_bfloat16* src = (sel ? g_hl : g_hh) +
                (size_t)(off + m0 + r) * HIDDEN + kt * BK + cc;
            __nv_bfloat16* dst = (sel ? sAl : sAh) + st * A_STAGE + r * LDA + cc;
            cp16(dst, src);
        }
    };

    // ---- B path: ldg fp32 W (n-contiguous) + split + sts, two k16 halves ----
    auto ldgB = [&](int kt, int h) {
#pragma unroll
        for (int i = 0; i < 2; i++) {
            int chunk = tid + i * 256;       // 512 chunks: 16 k-rows x 32 float4
            int kk = chunk >> 5;
            int c = (chunk & 31) << 2;
            float4 v = *reinterpret_cast<const float4*>(Wb + (size_t)(kt * BK + h * 16 + kk) * N + n0 + c);
            rb[4 * i + 0] = v.x; rb[4 * i + 1] = v.y; rb[4 * i + 2] = v.z; rb[4 * i + 3] = v.w;
        }
    };
    auto stsB = [&](int st, int h) {
        __nv_bfloat16* dh = sBh + st * B_STAGE;
        __nv_bfloat16* dl = sBl + st * B_STAGE;
#pragma unroll
        for (int i = 0; i < 2; i++) {
            int chunk = tid + i * 256;
            int kk = chunk >> 5;
            int c = (chunk & 31) << 2;
            uint2 hv, lv;
            split2(rb[4 * i + 0], rb[4 * i + 1], hv.x, lv.x);
            split2(rb[4 * i + 2], rb[4 * i + 3], hv.y, lv.y);
            *reinterpret_cast<uint2*>(dh + (h * 16 + kk) * LDB + c) = hv;
            *reinterpret_cast<uint2*>(dl + (h * 16 + kk) * LDB + c) = lv;
        }
    };

    float acc[4][4][4];
#pragma unroll
    for (int mi = 0; mi < 4; mi++)
#pragma unroll
        for (int ni = 0; ni < 4; ni++)
#pragma unroll
            for (int q = 0; q < 4; q++) acc[mi][ni][q] = 0.f;

    const int wid = tid >> 5;
    const int lane = tid & 31;
    const int wm = (wid & 1) * 64;
    const int wn = (wid >> 1) * 32;
    const int g = lane >> 2;
    const int tg = lane & 3;

    const int aRow = (lane & 15);
    const int aColOff = (lane >> 4) << 3;
    const int bKrow = (lane & 15);
    const int bColOff = (lane >> 4) << 3;

    const uint32_t sAh_u = (uint32_t)__cvta_generic_to_shared(sAh);
    const uint32_t sAl_u = (uint32_t)__cvta_generic_to_shared(sAl);
    const uint32_t sBh_u = (uint32_t)__cvta_generic_to_shared(sBh);
    const uint32_t sBl_u = (uint32_t)__cvta_generic_to_shared(sBl);

    constexpr int KT = K / BK;

    // prologue: fill stage 0
    if (PHASE == 1) {
        ldgA(0, 0); stsA(0, 0);
        ldgA(0, 1); stsA(0, 1);
    } else {
        cpA(0, 0);
        asm volatile("cp.async.commit_group;\n");
    }
    ldgB(0, 0); stsB(0, 0);
    ldgB(0, 1); stsB(0, 1);
    if (PHASE == 2) asm volatile("cp.async.wait_group 0;\n");
    __syncthreads();

    // MMA block for one k16 step on stage st
    auto mma_block = [&](int st, int ks) {
        const uint32_t aBaseH = sAh_u + (uint32_t)(st * A_STAGE) * 2u;
        const uint32_t aBaseL = sAl_u + (uint32_t)(st * A_STAGE) * 2u;
        const uint32_t bBaseH = sBh_u + (uint32_t)(st * B_STAGE) * 2u;
        const uint32_t bBaseL = sBl_u + (uint32_t)(st * B_STAGE) * 2u;
        uint32_t bh[4][2], bl[4][2];
#pragma unroll
        for (int nj = 0; nj < 2; nj++) {
            uint32_t boff = (uint32_t)((ks * 16 + bKrow) * LDB + wn + nj * 16 + bColOff) << 1;
            ldsm_x4_t(bh[2 * nj][0], bh[2 * nj][1], bh[2 * nj + 1][0], bh[2 * nj + 1][1], bBaseH + boff);
            ldsm_x4_t(bl[2 * nj][0], bl[2 * nj][1], bl[2 * nj + 1][0], bl[2 * nj + 1][1], bBaseL + boff);
        }
#pragma unroll
        for (int mi = 0; mi < 4; mi++) {
            uint32_t ah[4], al[4];
            uint32_t aoff = (uint32_t)((wm + mi * 16 + aRow) * LDA + ks * 16 + aColOff) << 1;
            ldsm_x4(ah[0], ah[1], ah[2], ah[3], aBaseH + aoff);
            ldsm_x4(al[0], al[1], al[2], al[3], aBaseL + aoff);
#pragma unroll
            for (int ni = 0; ni < 4; ni++) {
                mma_bf16(acc[mi][ni], ah, bh[ni][0], bh[ni][1]);
                mma_bf16(acc[mi][ni], ah, bl[ni][0], bl[ni][1]);
                mma_bf16(acc[mi][ni], al, bh[ni][0], bh[ni][1]);
            }
        }
    };

    for (int kt = 0; kt < KT; kt++) {
        const int st = kt & 1;
        const bool pf = (kt + 1 < KT);
        if (pf) {
            if (PHASE == 2) {
                cpA(st ^ 1, kt + 1);
                asm volatile("cp.async.commit_group;\n");
            } else {
                ldgA(kt + 1, 0);
            }
            ldgB(kt + 1, 0);
        }
        mma_block(st, 0);
        if (pf) {
            if (PHASE == 1) { stsA(st ^ 1, 0); ldgA(kt + 1, 1); }
            stsB(st ^ 1, 0);
            ldgB(kt + 1, 1);
        }
        mma_block(st, 1);
        if (pf) {
            if (PHASE == 1) stsA(st ^ 1, 1);
            stsB(st ^ 1, 1);
            if (PHASE == 2) asm volatile("cp.async.wait_group 0;\n");
        }
        __syncthreads();
    }

    // ---- epilogue ----
#pragma unroll
    for (int mi = 0; mi < 4; mi++) {
#pragma unroll
        for (int rr = 0; rr < 2; rr++) {
            int rloc = wm + mi * 16 + g + rr * 8;
            int row = m0 + rloc;
            if (row >= cnt) continue;
            if (PHASE == 1) {
                size_t base = (size_t)(off + row) * HIDDEN + n0;
#pragma unroll
                for (int ni = 0; ni < 4; ni++) {
                    int col = wn + ni * 8 + 2 * tg;
                    float v0 = gelu_exact(acc[mi][ni][rr * 2 + 0] + bias[n0 + col]);
                    float v1 = gelu_exact(acc[mi][ni][rr * 2 + 1] + bias[n0 + col + 1]);
                    uint32_t hv, lv;
                    split2(v0, v1, hv, lv);
                    *reinterpret_cast<uint32_t*>(g_hh + base + col) = hv;
                    *reinterpret_cast<uint32_t*>(g_hl + base + col) = lv;
                }
            } else {
                int t  = g_tok[e * MAXROWS + row];
                int kk = g_kslot[e * MAXROWS + row];
                float* outp = g_slot + ((size_t)t * 2 + kk) * EMBED + n0;
#pragma unroll
                for (int ni = 0; ni < 4; ni++) {
                    int col = wn + ni * 8 + 2 * tg;
                    outp[col]     = acc[mi][ni][rr * 2 + 0] + bias[n0 + col];
                    outp[col + 1] = acc[mi][ni][rr * 2 + 1] + bias[n0 + col + 1];
                }
            }
        }
    }
}

__global__ void combine_kernel(float* __restrict__ out) {
    int t = blockIdx.x;
    int i = threadIdx.x;
    float w0 = g_topw[t * 2 + 0], w1 = g_topw[t * 2 + 1];
    const float4* s0 = reinterpret_cast<const float4*>(g_slot + (size_t)t * 2 * EMBED);
    const float4* s1 = reinterpret_cast<const float4*>(g_slot + ((size_t)t * 2 + 1) * EMBED);
    float4 a = s0[i], b = s1[i];
    float4 r;
    r.x = w0 * a.x + w1 * b.x;
    r.y = w0 * a.y + w1 * b.y;
    r.z = w0 * a.z + w1 * b.z;
    r.w = w0 * a.w + w1 * b.w;
    reinterpret_cast<float4*>(out + (size_t)t * EMBED)[i] = r;
}

// ---------------- launch ----------------
extern "C" void kernel_launch(void* const* d_in, const int* in_sizes, int n_in,
                              void* d_out, int out_size) {
    const float* x   = (const float*)d_in[0];
    const float* gw  = (const float*)d_in[1];
    const float* w1  = (const float*)d_in[2];
    const float* b1  = (const float*)d_in[3];
    const float* w2  = (const float*)d_in[4];
    const float* b2  = (const float*)d_in[5];
    float* out = (float*)d_out;

    constexpr int SMEM_BYTES = (4 * 128 * 40 + 4 * 32 * 136) * 2;  // 75776 B
    cudaFuncSetAttribute(moe_gemm<1>, cudaFuncAttributeMaxDynamicSharedMemorySize, SMEM_BYTES);
    cudaFuncSetAttribute(moe_gemm<2>, cudaFuncAttributeMaxDynamicSharedMemorySize, SMEM_BYTES);

    init_kernel<<<1, 32>>>();
    router_kernel<<<NTOK / 8, 256>>>(x, gw);
    offsets_kernel<<<1, 32>>>();

    dim3 grid1(HIDDEN / 128, MAXROWS / 128, NEXP);  // (32, 16, 8); tiles beyond cnt exit
    moe_gemm<1><<<grid1, 256, SMEM_BYTES>>>(x, w1, b1);

    dim3 grid2(EMBED / 128, MAXROWS / 128, NEXP);   // (8, 16, 8)
    moe_gemm<2><<<grid2, 256, SMEM_BYTES>>>(nullptr, w2, b2);

    combine_kernel<<<NTOK, 256>>>(out);
}

// round 6
// speedup vs baseline: 1.7520x; 1.2588x over previous
#include <cuda_runtime.h>
#include <cuda_bf16.h>
#include <cstdint>
#include <math.h>

#define EMBED 1024
#define HIDDEN 4096
#define NEXP 8
#define NTOK 1024
#define MAXROWS 2048   // NTOK * TOP_K
#define KSPLIT2 4      // GEMM2 K-split factor

// ---------------- device scratch ----------------
__device__ __nv_bfloat16 g_hh[(MAXROWS + 128) * HIDDEN];
__device__ __nv_bfloat16 g_hl[(MAXROWS + 128) * HIDDEN];
__device__ float g_slot[NTOK * 2 * EMBED];
__device__ float g_topw[NTOK * 2];
__device__ int   g_expid[NTOK * 2];
__device__ int   g_tok[NEXP * MAXROWS];
__device__ int   g_kslot[NEXP * MAXROWS];
__device__ int   g_count[NEXP];
__device__ int   g_offset[NEXP];

// ---------------- small kernels ----------------
__global__ void init_kernel() {
    if (threadIdx.x < NEXP) g_count[threadIdx.x] = 0;
}

__global__ void zero_slot_kernel() {
    // NTOK*2*EMBED floats = 524288 float4
    reinterpret_cast<float4*>(g_slot)[blockIdx.x * 256 + threadIdx.x] =
        make_float4(0.f, 0.f, 0.f, 0.f);
}

__global__ void router_kernel(const float* __restrict__ x, const float* __restrict__ gw) {
    int warp = (blockIdx.x * blockDim.x + threadIdx.x) >> 5;
    int lane = threadIdx.x & 31;
    if (warp >= NTOK) return;
    const float* xr = x + (size_t)warp * EMBED;
    float acc[NEXP];
#pragma unroll
    for (int n = 0; n < NEXP; n++) acc[n] = 0.f;
    for (int d = lane; d < EMBED; d += 32) {
        float xv = xr[d];
#pragma unroll
        for (int n = 0; n < NEXP; n++) acc[n] += xv * gw[n * EMBED + d];
    }
#pragma unroll
    for (int n = 0; n < NEXP; n++)
#pragma unroll
        for (int o = 16; o > 0; o >>= 1) acc[n] += __shfl_xor_sync(0xffffffffu, acc[n], o);
    if (lane == 0) {
        float mx = acc[0];
#pragma unroll
        for (int n = 1; n < NEXP; n++) mx = fmaxf(mx, acc[n]);
        float p[NEXP], s = 0.f;
#pragma unroll
        for (int n = 0; n < NEXP; n++) { p[n] = expf(acc[n] - mx); s += p[n]; }
        float inv = 1.f / s;
#pragma unroll
        for (int n = 0; n < NEXP; n++) p[n] *= inv;
        int i0 = 0;
#pragma unroll
        for (int n = 1; n < NEXP; n++) if (p[n] > p[i0]) i0 = n;
        int i1 = (i0 == 0) ? 1 : 0;
#pragma unroll
        for (int n = 0; n < NEXP; n++) if (n != i0 && p[n] > p[i1]) i1 = n;
        float w0 = p[i0], w1 = p[i1];
        float rs = 1.f / (w0 + w1 + 1e-9f);
        g_topw[warp * 2 + 0] = w0 * rs;
        g_topw[warp * 2 + 1] = w1 * rs;
        g_expid[warp * 2 + 0] = i0;
        g_expid[warp * 2 + 1] = i1;
        int pos0 = atomicAdd(&g_count[i0], 1);
        g_tok[i0 * MAXROWS + pos0] = warp; g_kslot[i0 * MAXROWS + pos0] = 0;
        int pos1 = atomicAdd(&g_count[i1], 1);
        g_tok[i1 * MAXROWS + pos1] = warp; g_kslot[i1 * MAXROWS + pos1] = 1;
    }
}

__global__ void offsets_kernel() {
    if (threadIdx.x == 0) {
        int o = 0;
        for (int e = 0; e < NEXP; e++) { g_offset[e] = o; o += g_count[e]; }
    }
}

// ---------------- helpers ----------------
__device__ __forceinline__ float gelu_exact(float v) {
    return 0.5f * v * (1.0f + erff(v * 0.7071067811865476f));
}

__device__ __forceinline__ void split2(float x, float y, uint32_t& hi, uint32_t& lo) {
    __nv_bfloat162 h = __floats2bfloat162_rn(x, y);   // .x (low half) = x
    float rx = x - __bfloat162float(h.x);
    float ry = y - __bfloat162float(h.y);
    __nv_bfloat162 l = __floats2bfloat162_rn(rx, ry);
    hi = *reinterpret_cast<uint32_t*>(&h);
    lo = *reinterpret_cast<uint32_t*>(&l);
}

__device__ __forceinline__ void cp16(void* dst_smem, const void* src) {
    uint32_t d = (uint32_t)__cvta_generic_to_shared(dst_smem);
    asm volatile("cp.async.cg.shared.global [%0], [%1], 16;\n" ::"r"(d), "l"(src));
}

__device__ __forceinline__ void mma_bf16(float c[4], const uint32_t a[4], const uint32_t b0, const uint32_t b1) {
    asm volatile(
        "mma.sync.aligned.m16n8k16.row.col.f32.bf16.bf16.f32 "
        "{%0,%1,%2,%3}, {%4,%5,%6,%7}, {%8,%9}, {%0,%1,%2,%3};\n"
        : "+f"(c[0]), "+f"(c[1]), "+f"(c[2]), "+f"(c[3])
        : "r"(a[0]), "r"(a[1]), "r"(a[2]), "r"(a[3]), "r"(b0), "r"(b1));
}

__device__ __forceinline__ void ldsm_x4(uint32_t& r0, uint32_t& r1, uint32_t& r2, uint32_t& r3, uint32_t addr) {
    asm volatile("ldmatrix.sync.aligned.m8n8.x4.shared.b16 {%0,%1,%2,%3}, [%4];\n"
                 : "=r"(r0), "=r"(r1), "=r"(r2), "=r"(r3) : "r"(addr));
}

__device__ __forceinline__ void ldsm_x4_t(uint32_t& r0, uint32_t& r1, uint32_t& r2, uint32_t& r3, uint32_t addr) {
    asm volatile("ldmatrix.sync.aligned.m8n8.x4.trans.shared.b16 {%0,%1,%2,%3}, [%4];\n"
                 : "=r"(r0), "=r"(r1), "=r"(r2), "=r"(r3) : "r"(addr));
}

// ---------------- grouped expert GEMM (bf16x3, 2 CTAs/SM) ----------------
// PHASE 1: Hhi/Hlo[off+row,:] = split(gelu( X[tok[row],:] @ W1[e] + b1[e] ))  K=1024, N=4096
// PHASE 2 (split-K x4): slot[tok,k,:] += H[off+row, kq-slice] @ W2[e][kq-slice]  K=4096, N=1024
template <int PHASE>
__global__ void __launch_bounds__(256, 2) moe_gemm(const float* __restrict__ X,
                                                   const float* __restrict__ W,
                                                   const float* __restrict__ BiasAll) {
    constexpr int K = (PHASE == 1) ? EMBED : HIDDEN;
    constexpr int N = (PHASE == 1) ? HIDDEN : EMBED;
    constexpr int BM = 128, BN = 128, BK = 32;
    constexpr int LDA = BK + 8;    // 40 bf16 (80B)
    constexpr int LDB = BN + 8;    // 136 bf16 (272B)
    constexpr int A_STAGE = BM * LDA;
    constexpr int B_STAGE = BK * LDB;
    constexpr int KT = K / BK;

    extern __shared__ __nv_bfloat16 smem[];
    __nv_bfloat16* sAh = smem;
    __nv_bfloat16* sAl = smem + 2 * A_STAGE;
    __nv_bfloat16* sBh = smem + 4 * A_STAGE;
    __nv_bfloat16* sBl = smem + 4 * A_STAGE + 2 * B_STAGE;
    __shared__ const float* rowptr[BM];

    int e, kt0, kt1;
    if (PHASE == 1) { e = blockIdx.z; kt0 = 0; kt1 = KT; }
    else { e = blockIdx.z >> 2; int kq = blockIdx.z & 3; kt0 = kq * (KT / KSPLIT2); kt1 = kt0 + KT / KSPLIT2; }

    const int cnt = g_count[e];
    const int m0 = blockIdx.y * BM;
    if (m0 >= cnt) return;
    const int n0 = blockIdx.x * BN;
    const int off = g_offset[e];
    const float* Wb = W + (size_t)e * K * N;
    const float* bias = BiasAll + (size_t)e * N;
    const int tid = threadIdx.x;

    if (PHASE == 1) {
        for (int r = tid; r < BM; r += 256) {
            int row = m0 + r;
            rowptr[r] = (row < cnt) ? (X + (size_t)g_tok[e * MAXROWS + row] * EMBED) : nullptr;
        }
        __syncthreads();
    }

    float ra[8], rb[8];

    auto ldgA = [&](int kt, int h) {
#pragma unroll
        for (int i = 0; i < 2; i++) {
            int chunk = tid + i * 256;
            int r = chunk >> 2;
            int cc = (chunk & 3) << 2;
            const float* p = rowptr[r];
            float4 v = make_float4(0.f, 0.f, 0.f, 0.f);
            if (p) v = *reinterpret_cast<const float4*>(p + kt * BK + h * 16 + cc);
            ra[4 * i + 0] = v.x; ra[4 * i + 1] = v.y; ra[4 * i + 2] = v.z; ra[4 * i + 3] = v.w;
        }
    };
    auto stsA = [&](int st, int h) {
        __nv_bfloat16* dh = sAh + st * A_STAGE;
        __nv_bfloat16* dl = sAl + st * A_STAGE;
#pragma unroll
        for (int i = 0; i < 2; i++) {
            int chunk = tid + i * 256;
            int r = chunk >> 2;
            int cc = (chunk & 3) << 2;
            uint2 hv, lv;
            split2(ra[4 * i + 0], ra[4 * i + 1], hv.x, lv.x);
            split2(ra[4 * i + 2], ra[4 * i + 3], hv.y, lv.y);
            *reinterpret_cast<uint2*>(dh + r * LDA + h * 16 + cc) = hv;
            *reinterpret_cast<uint2*>(dl + r * LDA + h * 16 + cc) = lv;
        }
    };
    auto cpA = [&](int st, int kt) {
#pragma unroll
        for (int i = 0; i < 4; i++) {
            int chunk = tid + i * 256;
            int sel = chunk >> 9;
            int c2 = chunk & 511;
            int r = c2 >> 2;
            int cc = (c2 & 3) << 3;
            const __nv_bfloat16* src = (sel ? g_hl : g_hh) +
                (size_t)(off + m0 + r) * HIDDEN + kt * BK + cc;
            __nv_bfloat16* dst = (sel ? sAl : sAh) + st * A_STAGE + r * LDA + cc;
            cp16(dst, src);
        }
    };

    auto ldgB = [&](int kt, int h) {
#pragma unroll
        for (int i = 0; i < 2; i++) {
            int chunk = tid + i * 256;
            int kk = chunk >> 5;
            int c = (chunk & 31) << 2;
            float4 v = *reinterpret_cast<const float4*>(Wb + (size_t)(kt * BK + h * 16 + kk) * N + n0 + c);
            rb[4 * i + 0] = v.x; rb[4 * i + 1] = v.y; rb[4 * i + 2] = v.z; rb[4 * i + 3] = v.w;
        }
    };
    auto stsB = [&](int st, int h) {
        __nv_bfloat16* dh = sBh + st * B_STAGE;
        __nv_bfloat16* dl = sBl + st * B_STAGE;
#pragma unroll
        for (int i = 0; i < 2; i++) {
            int chunk = tid + i * 256;
            int kk = chunk >> 5;
            int c = (chunk & 31) << 2;
            uint2 hv, lv;
            split2(rb[4 * i + 0], rb[4 * i + 1], hv.x, lv.x);
            split2(rb[4 * i + 2], rb[4 * i + 3], hv.y, lv.y);
            *reinterpret_cast<uint2*>(dh + (h * 16 + kk) * LDB + c) = hv;
            *reinterpret_cast<uint2*>(dl + (h * 16 + kk) * LDB + c) = lv;
        }
    };

    float acc[4][4][4];
#pragma unroll
    for (int mi = 0; mi < 4; mi++)
#pragma unroll
        for (int ni = 0; ni < 4; ni++)
#pragma unroll
            for (int q = 0; q < 4; q++) acc[mi][ni][q] = 0.f;

    const int wid = tid >> 5;
    const int lane = tid & 31;
    const int wm = (wid & 1) * 64;
    const int wn = (wid >> 1) * 32;
    const int g = lane >> 2;
    const int tg = lane & 3;

    const int aRow = (lane & 15);
    const int aColOff = (lane >> 4) << 3;
    const int bKrow = (lane & 15);
    const int bColOff = (lane >> 4) << 3;

    const uint32_t sAh_u = (uint32_t)__cvta_generic_to_shared(sAh);
    const uint32_t sAl_u = (uint32_t)__cvta_generic_to_shared(sAl);
    const uint32_t sBh_u = (uint32_t)__cvta_generic_to_shared(sBh);
    const uint32_t sBl_u = (uint32_t)__cvta_generic_to_shared(sBl);

    // prologue: fill stage 0 with k-tile kt0
    if (PHASE == 1) {
        ldgA(kt0, 0); stsA(0, 0);
        ldgA(kt0, 1); stsA(0, 1);
    } else {
        cpA(0, kt0);
        asm volatile("cp.async.commit_group;\n");
    }
    ldgB(kt0, 0); stsB(0, 0);
    ldgB(kt0, 1); stsB(0, 1);
    if (PHASE == 2) asm volatile("cp.async.wait_group 0;\n");
    __syncthreads();

    auto mma_block = [&](int st, int ks) {
        const uint32_t aBaseH = sAh_u + (uint32_t)(st * A_STAGE) * 2u;
        const uint32_t aBaseL = sAl_u + (uint32_t)(st * A_STAGE) * 2u;
        const uint32_t bBaseH = sBh_u + (uint32_t)(st * B_STAGE) * 2u;
        const uint32_t bBaseL = sBl_u + (uint32_t)(st * B_STAGE) * 2u;
        uint32_t bh[4][2], bl[4][2];
#pragma unroll
        for (int nj = 0; nj < 2; nj++) {
            uint32_t boff = (uint32_t)((ks * 16 + bKrow) * LDB + wn + nj * 16 + bColOff) << 1;
            ldsm_x4_t(bh[2 * nj][0], bh[2 * nj][1], bh[2 * nj + 1][0], bh[2 * nj + 1][1], bBaseH + boff);
            ldsm_x4_t(bl[2 * nj][0], bl[2 * nj][1], bl[2 * nj + 1][0], bl[2 * nj + 1][1], bBaseL + boff);
        }
#pragma unroll
        for (int mi = 0; mi < 4; mi++) {
            uint32_t ah[4], al[4];
            uint32_t aoff = (uint32_t)((wm + mi * 16 + aRow) * LDA + ks * 16 + aColOff) << 1;
            ldsm_x4(ah[0], ah[1], ah[2], ah[3], aBaseH + aoff);
            ldsm_x4(al[0], al[1], al[2], al[3], aBaseL + aoff);
#pragma unroll
            for (int ni = 0; ni < 4; ni++) {
                mma_bf16(acc[mi][ni], ah, bh[ni][0], bh[ni][1]);
                mma_bf16(acc[mi][ni], ah, bl[ni][0], bl[ni][1]);
                mma_bf16(acc[mi][ni], al, bh[ni][0], bh[ni][1]);
            }
        }
    };

    for (int kt = kt0; kt < kt1; kt++) {
        const int st = (kt - kt0) & 1;
        const bool pf = (kt + 1 < kt1);
        if (pf) {
            if (PHASE == 2) {
                cpA(st ^ 1, kt + 1);
                asm volatile("cp.async.commit_group;\n");
            } else {
                ldgA(kt + 1, 0);
            }
            ldgB(kt + 1, 0);
        }
        mma_block(st, 0);
        if (pf) {
            if (PHASE == 1) { stsA(st ^ 1, 0); ldgA(kt + 1, 1); }
            stsB(st ^ 1, 0);
            ldgB(kt + 1, 1);
        }
        mma_block(st, 1);
        if (pf) {
            if (PHASE == 1) stsA(st ^ 1, 1);
            stsB(st ^ 1, 1);
            if (PHASE == 2) asm volatile("cp.async.wait_group 0;\n");
        }
        __syncthreads();
    }

    // ---- epilogue ----
#pragma unroll
    for (int mi = 0; mi < 4; mi++) {
#pragma unroll
        for (int rr = 0; rr < 2; rr++) {
            int rloc = wm + mi * 16 + g + rr * 8;
            int row = m0 + rloc;
            if (row >= cnt) continue;
            if (PHASE == 1) {
                size_t base = (size_t)(off + row) * HIDDEN + n0;
#pragma unroll
                for (int ni = 0; ni < 4; ni++) {
                    int col = wn + ni * 8 + 2 * tg;
                    float v0 = gelu_exact(acc[mi][ni][rr * 2 + 0] + bias[n0 + col]);
                    float v1 = gelu_exact(acc[mi][ni][rr * 2 + 1] + bias[n0 + col + 1]);
                    uint32_t hv, lv;
                    split2(v0, v1, hv, lv);
                    *reinterpret_cast<uint32_t*>(g_hh + base + col) = hv;
                    *reinterpret_cast<uint32_t*>(g_hl + base + col) = lv;
                }
            } else {
                int t  = g_tok[e * MAXROWS + row];
                int kk = g_kslot[e * MAXROWS + row];
                float* outp = g_slot + ((size_t)t * 2 + kk) * EMBED + n0;
#pragma unroll
                for (int ni = 0; ni < 4; ni++) {
                    int col = wn + ni * 8 + 2 * tg;
                    atomicAdd(&outp[col],     acc[mi][ni][rr * 2 + 0]);
                    atomicAdd(&outp[col + 1], acc[mi][ni][rr * 2 + 1]);
                }
            }
        }
    }
}

__global__ void combine_kernel(float* __restrict__ out, const float* __restrict__ b2) {
    int t = blockIdx.x;
    int i = threadIdx.x;  // 256 threads x float4 = 1024 floats
    float w0 = g_topw[t * 2 + 0], w1 = g_topw[t * 2 + 1];
    int e0 = g_expid[t * 2 + 0],  e1 = g_expid[t * 2 + 1];
    float4 a = reinterpret_cast<const float4*>(g_slot + (size_t)t * 2 * EMBED)[i];
    float4 b = reinterpret_cast<const float4*>(g_slot + ((size_t)t * 2 + 1) * EMBED)[i];
    float4 ba = reinterpret_cast<const float4*>(b2 + (size_t)e0 * EMBED)[i];
    float4 bb = reinterpret_cast<const float4*>(b2 + (size_t)e1 * EMBED)[i];
    float4 r;
    r.x = w0 * (a.x + ba.x) + w1 * (b.x + bb.x);
    r.y = w0 * (a.y + ba.y) + w1 * (b.y + bb.y);
    r.z = w0 * (a.z + ba.z) + w1 * (b.z + bb.z);
    r.w = w0 * (a.w + ba.w) + w1 * (b.w + bb.w);
    reinterpret_cast<float4*>(out + (size_t)t * EMBED)[i] = r;
}

// ---------------- launch ----------------
extern "C" void kernel_launch(void* const* d_in, const int* in_sizes, int n_in,
                              void* d_out, int out_size) {
    const float* x   = (const float*)d_in[0];
    const float* gw  = (const float*)d_in[1];
    const float* w1  = (const float*)d_in[2];
    const float* b1  = (const float*)d_in[3];
    const float* w2  = (const float*)d_in[4];
    const float* b2  = (const float*)d_in[5];
    float* out = (float*)d_out;

    constexpr int SMEM_BYTES = (4 * 128 * 40 + 4 * 32 * 136) * 2;  // 75776 B
    cudaFuncSetAttribute(moe_gemm<1>, cudaFuncAttributeMaxDynamicSharedMemorySize, SMEM_BYTES);
    cudaFuncSetAttribute(moe_gemm<2>, cudaFuncAttributeMaxDynamicSharedMemorySize, SMEM_BYTES);

    init_kernel<<<1, 32>>>();
    zero_slot_kernel<<<NTOK * 2 * EMBED / 1024, 256>>>();
    router_kernel<<<NTOK / 8, 256>>>(x, gw);
    offsets_kernel<<<1, 32>>>();

    dim3 grid1(HIDDEN / 128, MAXROWS / 128, NEXP);            // (32, 16, 8)
    moe_gemm<1><<<grid1, 256, SMEM_BYTES>>>(x, w1, b1);

    dim3 grid2(EMBED / 128, MAXROWS / 128, NEXP * KSPLIT2);   // (8, 16, 32)
    moe_gemm<2><<<grid2, 256, SMEM_BYTES>>>(nullptr, w2, b2);

    combine_kernel<<<NTOK, 256>>>(out, b2);
}

// round 7
// speedup vs baseline: 1.7805x; 1.0163x over previous
#include <cuda_runtime.h>
#include <cuda_bf16.h>
#include <cstdint>
#include <math.h>

#define EMBED 1024
#define HIDDEN 4096
#define NEXP 8
#define NTOK 1024
#define MAXROWS 2048   // NTOK * TOP_K
#define KSPLIT2 8      // GEMM2 K-split factor

// ---------------- device scratch ----------------
__device__ __nv_bfloat16 g_hh[(MAXROWS + 128) * HIDDEN];
__device__ __nv_bfloat16 g_hl[(MAXROWS + 128) * HIDDEN];
__device__ float g_slot[NTOK * 2 * EMBED];
__device__ float g_topw[NTOK * 2];
__device__ int   g_expid[NTOK * 2];
__device__ int   g_tok[NEXP * MAXROWS];
__device__ int   g_kslot[NEXP * MAXROWS];
__device__ int   g_count[NEXP];

// ---------------- small kernels ----------------
// init counters + zero the split-K accumulation buffer in one launch
__global__ void init_zero_kernel() {
    if (blockIdx.x == 0 && threadIdx.x < NEXP) g_count[threadIdx.x] = 0;
    reinterpret_cast<float4*>(g_slot)[blockIdx.x * 256 + threadIdx.x] =
        make_float4(0.f, 0.f, 0.f, 0.f);
}

__global__ void router_kernel(const float* __restrict__ x, const float* __restrict__ gw) {
    int warp = (blockIdx.x * blockDim.x + threadIdx.x) >> 5;
    int lane = threadIdx.x & 31;
    if (warp >= NTOK) return;
    const float* xr = x + (size_t)warp * EMBED;
    float acc[NEXP];
#pragma unroll
    for (int n = 0; n < NEXP; n++) acc[n] = 0.f;
    for (int d = lane; d < EMBED; d += 32) {
        float xv = xr[d];
#pragma unroll
        for (int n = 0; n < NEXP; n++) acc[n] += xv * gw[n * EMBED + d];
    }
#pragma unroll
    for (int n = 0; n < NEXP; n++)
#pragma unroll
        for (int o = 16; o > 0; o >>= 1) acc[n] += __shfl_xor_sync(0xffffffffu, acc[n], o);
    if (lane == 0) {
        float mx = acc[0];
#pragma unroll
        for (int n = 1; n < NEXP; n++) mx = fmaxf(mx, acc[n]);
        float p[NEXP], s = 0.f;
#pragma unroll
        for (int n = 0; n < NEXP; n++) { p[n] = expf(acc[n] - mx); s += p[n]; }
        float inv = 1.f / s;
#pragma unroll
        for (int n = 0; n < NEXP; n++) p[n] *= inv;
        int i0 = 0;
#pragma unroll
        for (int n = 1; n < NEXP; n++) if (p[n] > p[i0]) i0 = n;
        int i1 = (i0 == 0) ? 1 : 0;
#pragma unroll
        for (int n = 0; n < NEXP; n++) if (n != i0 && p[n] > p[i1]) i1 = n;
        float w0 = p[i0], w1 = p[i1];
        float rs = 1.f / (w0 + w1 + 1e-9f);
        g_topw[warp * 2 + 0] = w0 * rs;
        g_topw[warp * 2 + 1] = w1 * rs;
        g_expid[warp * 2 + 0] = i0;
        g_expid[warp * 2 + 1] = i1;
        int pos0 = atomicAdd(&g_count[i0], 1);
        g_tok[i0 * MAXROWS + pos0] = warp; g_kslot[i0 * MAXROWS + pos0] = 0;
        int pos1 = atomicAdd(&g_count[i1], 1);
        g_tok[i1 * MAXROWS + pos1] = warp; g_kslot[i1 * MAXROWS + pos1] = 1;
    }
}

// ---------------- helpers ----------------
__device__ __forceinline__ float gelu_exact(float v) {
    return 0.5f * v * (1.0f + erff(v * 0.7071067811865476f));
}

__device__ __forceinline__ void split2(float x, float y, uint32_t& hi, uint32_t& lo) {
    __nv_bfloat162 h = __floats2bfloat162_rn(x, y);   // .x (low half) = x
    float rx = x - __bfloat162float(h.x);
    float ry = y - __bfloat162float(h.y);
    __nv_bfloat162 l = __floats2bfloat162_rn(rx, ry);
    hi = *reinterpret_cast<uint32_t*>(&h);
    lo = *reinterpret_cast<uint32_t*>(&l);
}

__device__ __forceinline__ void cp16(void* dst_smem, const void* src) {
    uint32_t d = (uint32_t)__cvta_generic_to_shared(dst_smem);
    asm volatile("cp.async.cg.shared.global [%0], [%1], 16;\n" ::"r"(d), "l"(src));
}

__device__ __forceinline__ void mma_bf16(float c[4], const uint32_t a[4], const uint32_t b0, const uint32_t b1) {
    asm volatile(
        "mma.sync.aligned.m16n8k16.row.col.f32.bf16.bf16.f32 "
        "{%0,%1,%2,%3}, {%4,%5,%6,%7}, {%8,%9}, {%0,%1,%2,%3};\n"
        : "+f"(c[0]), "+f"(c[1]), "+f"(c[2]), "+f"(c[3])
        : "r"(a[0]), "r"(a[1]), "r"(a[2]), "r"(a[3]), "r"(b0), "r"(b1));
}

__device__ __forceinline__ void ldsm_x4(uint32_t& r0, uint32_t& r1, uint32_t& r2, uint32_t& r3, uint32_t addr) {
    asm volatile("ldmatrix.sync.aligned.m8n8.x4.shared.b16 {%0,%1,%2,%3}, [%4];\n"
                 : "=r"(r0), "=r"(r1), "=r"(r2), "=r"(r3) : "r"(addr));
}

__device__ __forceinline__ void ldsm_x4_t(uint32_t& r0, uint32_t& r1, uint32_t& r2, uint32_t& r3, uint32_t addr) {
    asm volatile("ldmatrix.sync.aligned.m8n8.x4.trans.shared.b16 {%0,%1,%2,%3}, [%4];\n"
                 : "=r"(r0), "=r"(r1), "=r"(r2), "=r"(r3) : "r"(addr));
}

// ---------------- grouped expert GEMM (bf16x3, 2 CTAs/SM) ----------------
// PHASE 1: Hhi/Hlo[off+row,:] = split(gelu( X[tok[row],:] @ W1[e] + b1[e] ))  K=1024, N=4096
// PHASE 2 (split-K x8): slot[tok,k,:] += H[off+row, kq-slice] @ W2[e][kq-slice]  K=4096, N=1024
template <int PHASE>
__global__ void __launch_bounds__(256, 2) moe_gemm(const float* __restrict__ X,
                                                   const float* __restrict__ W,
                                                   const float* __restrict__ BiasAll) {
    constexpr int K = (PHASE == 1) ? EMBED : HIDDEN;
    constexpr int N = (PHASE == 1) ? HIDDEN : EMBED;
    constexpr int BM = 128, BN = 128, BK = 32;
    constexpr int LDA = BK + 8;    // 40 bf16 (80B)
    constexpr int LDB = BN + 8;    // 136 bf16 (272B)
    constexpr int A_STAGE = BM * LDA;
    constexpr int B_STAGE = BK * LDB;
    constexpr int KT = K / BK;

    extern __shared__ __nv_bfloat16 smem[];
    __nv_bfloat16* sAh = smem;
    __nv_bfloat16* sAl = smem + 2 * A_STAGE;
    __nv_bfloat16* sBh = smem + 4 * A_STAGE;
    __nv_bfloat16* sBl = smem + 4 * A_STAGE + 2 * B_STAGE;
    __shared__ const float* rowptr[BM];

    int e, kt0, kt1;
    if (PHASE == 1) { e = blockIdx.z; kt0 = 0; kt1 = KT; }
    else { e = blockIdx.z >> 3; int kq = blockIdx.z & 7; kt0 = kq * (KT / KSPLIT2); kt1 = kt0 + KT / KSPLIT2; }

    const int cnt = g_count[e];
    const int m0 = blockIdx.y * BM;
    if (m0 >= cnt) return;
    // inline exclusive prefix over 8 counters (replaces offsets_kernel)
    int off = 0;
#pragma unroll
    for (int i = 0; i < NEXP; i++) off += (i < e) ? g_count[i] : 0;

    const int n0 = blockIdx.x * BN;
    const float* Wb = W + (size_t)e * K * N;
    const float* bias = BiasAll + (size_t)e * N;
    const int tid = threadIdx.x;

    if (PHASE == 1) {
        for (int r = tid; r < BM; r += 256) {
            int row = m0 + r;
            rowptr[r] = (row < cnt) ? (X + (size_t)g_tok[e * MAXROWS + row] * EMBED) : nullptr;
        }
        __syncthreads();
    }

    float ra[8], rb[8];

    auto ldgA = [&](int kt, int h) {
#pragma unroll
        for (int i = 0; i < 2; i++) {
            int chunk = tid + i * 256;
            int r = chunk >> 2;
            int cc = (chunk & 3) << 2;
            const float* p = rowptr[r];
            float4 v = make_float4(0.f, 0.f, 0.f, 0.f);
            if (p) v = *reinterpret_cast<const float4*>(p + kt * BK + h * 16 + cc);
            ra[4 * i + 0] = v.x; ra[4 * i + 1] = v.y; ra[4 * i + 2] = v.z; ra[4 * i + 3] = v.w;
        }
    };
    auto stsA = [&](int st, int h) {
        __nv_bfloat16* dh = sAh + st * A_STAGE;
        __nv_bfloat16* dl = sAl + st * A_STAGE;
#pragma unroll
        for (int i = 0; i < 2; i++) {
            int chunk = tid + i * 256;
            int r = chunk >> 2;
            int cc = (chunk & 3) << 2;
            uint2 hv, lv;
            split2(ra[4 * i + 0], ra[4 * i + 1], hv.x, lv.x);
            split2(ra[4 * i + 2], ra[4 * i + 3], hv.y, lv.y);
            *reinterpret_cast<uint2*>(dh + r * LDA + h * 16 + cc) = hv;
            *reinterpret_cast<uint2*>(dl + r * LDA + h * 16 + cc) = lv;
        }
    };
    auto cpA = [&](int st, int kt) {
#pragma unroll
        for (int i = 0; i < 4; i++) {
            int chunk = tid + i * 256;
            int sel = chunk >> 9;
            int c2 = chunk & 511;
            int r = c2 >> 2;
            int cc = (c2 & 3) << 3;
            const __nv_bfloat16* src = (sel ? g_hl : g_hh) +
                (size_t)(off + m0 + r) * HIDDEN + kt * BK + cc;
            __nv_bfloat16* dst = (sel ? sAl : sAh) + st * A_STAGE + r * LDA + cc;
            cp16(dst, src);
        }
    };

    auto ldgB = [&](int kt, int h) {
#pragma unroll
        for (int i = 0; i < 2; i++) {
            int chunk = tid + i * 256;
            int kk = chunk >> 5;
            int c = (chunk & 31) << 2;
            float4 v = *reinterpret_cast<const float4*>(Wb + (size_t)(kt * BK + h * 16 + kk) * N + n0 + c);
            rb[4 * i + 0] = v.x; rb[4 * i + 1] = v.y; rb[4 * i + 2] = v.z; rb[4 * i + 3] = v.w;
        }
    };
    auto stsB = [&](int st, int h) {
        __nv_bfloat16* dh = sBh + st * B_STAGE;
        __nv_bfloat16* dl = sBl + st * B_STAGE;
#pragma unroll
        for (int i = 0; i < 2; i++) {
            int chunk = tid + i * 256;
            int kk = chunk >> 5;
            int c = (chunk & 31) << 2;
            uint2 hv, lv;
            split2(rb[4 * i + 0], rb[4 * i + 1], hv.x, lv.x);
            split2(rb[4 * i + 2], rb[4 * i + 3], hv.y, lv.y);
            *reinterpret_cast<uint2*>(dh + (h * 16 + kk) * LDB + c) = hv;
            *reinterpret_cast<uint2*>(dl + (h * 16 + kk) * LDB + c) = lv;
        }
    };

    float acc[4][4][4];
#pragma unroll
    for (int mi = 0; mi < 4; mi++)
#pragma unroll
        for (int ni = 0; ni < 4; ni++)
#pragma unroll
            for (int q = 0; q < 4; q++) acc[mi][ni][q] = 0.f;

    const int wid = tid >> 5;
    const int lane = tid & 31;
    const int wm = (wid & 1) * 64;
    const int wn = (wid >> 1) * 32;
    const int g = lane >> 2;
    const int tg = lane & 3;

    const int aRow = (lane & 15);
    const int aColOff = (lane >> 4) << 3;
    const int bKrow = (lane & 15);
    const int bColOff = (lane >> 4) << 3;

    const uint32_t sAh_u = (uint32_t)__cvta_generic_to_shared(sAh);
    const uint32_t sAl_u = (uint32_t)__cvta_generic_to_shared(sAl);
    const uint32_t sBh_u = (uint32_t)__cvta_generic_to_shared(sBh);
    const uint32_t sBl_u = (uint32_t)__cvta_generic_to_shared(sBl);

    // prologue: fill stage 0 with k-tile kt0
    if (PHASE == 1) {
        ldgA(kt0, 0); stsA(0, 0);
        ldgA(kt0, 1); stsA(0, 1);
    } else {
        cpA(0, kt0);
        asm volatile("cp.async.commit_group;\n");
    }
    ldgB(kt0, 0); stsB(0, 0);
    ldgB(kt0, 1); stsB(0, 1);
    if (PHASE == 2) asm volatile("cp.async.wait_group 0;\n");
    __syncthreads();

    auto mma_block = [&](int st, int ks) {
        const uint32_t aBaseH = sAh_u + (uint32_t)(st * A_STAGE) * 2u;
        const uint32_t aBaseL = sAl_u + (uint32_t)(st * A_STAGE) * 2u;
        const uint32_t bBaseH = sBh_u + (uint32_t)(st * B_STAGE) * 2u;
        const uint32_t bBaseL = sBl_u + (uint32_t)(st * B_STAGE) * 2u;
        uint32_t bh[4][2], bl[4][2];
#pragma unroll
        for (int nj = 0; nj < 2; nj++) {
            uint32_t boff = (uint32_t)((ks * 16 + bKrow) * LDB + wn + nj * 16 + bColOff) << 1;
            ldsm_x4_t(bh[2 * nj][0], bh[2 * nj][1], bh[2 * nj + 1][0], bh[2 * nj + 1][1], bBaseH + boff);
            ldsm_x4_t(bl[2 * nj][0], bl[2 * nj][1], bl[2 * nj + 1][0], bl[2 * nj + 1][1], bBaseL + boff);
        }
#pragma unroll
        for (int mi = 0; mi < 4; mi++) {
            uint32_t ah[4], al[4];
            uint32_t aoff = (uint32_t)((wm + mi * 16 + aRow) * LDA + ks * 16 + aColOff) << 1;
            ldsm_x4(ah[0], ah[1], ah[2], ah[3], aBaseH + aoff);
            ldsm_x4(al[0], al[1], al[2], al[3], aBaseL + aoff);
#pragma unroll
            for (int ni = 0; ni < 4; ni++) {
                mma_bf16(acc[mi][ni], ah, bh[ni][0], bh[ni][1]);
                mma_bf16(acc[mi][ni], ah, bl[ni][0], bl[ni][1]);
                mma_bf16(acc[mi][ni], al, bh[ni][0], bh[ni][1]);
            }
        }
    };

    for (int kt = kt0; kt < kt1; kt++) {
        const int st = (kt - kt0) & 1;
        const bool pf = (kt + 1 < kt1);
        if (pf) {
            if (PHASE == 2) {
                cpA(st ^ 1, kt + 1);
                asm volatile("cp.async.commit_group;\n");
            } else {
                ldgA(kt + 1, 0);
            }
            ldgB(kt + 1, 0);
        }
        mma_block(st, 0);
        if (pf) {
            if (PHASE == 1) { stsA(st ^ 1, 0); ldgA(kt + 1, 1); }
            stsB(st ^ 1, 0);
            ldgB(kt + 1, 1);
        }
        mma_block(st, 1);
        if (pf) {
            if (PHASE == 1) stsA(st ^ 1, 1);
            stsB(st ^ 1, 1);
            if (PHASE == 2) asm volatile("cp.async.wait_group 0;\n");
        }
        __syncthreads();
    }

    // ---- epilogue ----
#pragma unroll
    for (int mi = 0; mi < 4; mi++) {
#pragma unroll
        for (int rr = 0; rr < 2; rr++) {
            int rloc = wm + mi * 16 + g + rr * 8;
            int row = m0 + rloc;
            if (row >= cnt) continue;
            if (PHASE == 1) {
                size_t base = (size_t)(off + row) * HIDDEN + n0;
#pragma unroll
                for (int ni = 0; ni < 4; ni++) {
                    int col = wn + ni * 8 + 2 * tg;
                    float v0 = gelu_exact(acc[mi][ni][rr * 2 + 0] + bias[n0 + col]);
                    float v1 = gelu_exact(acc[mi][ni][rr * 2 + 1] + bias[n0 + col + 1]);
                    uint32_t hv, lv;
                    split2(v0, v1, hv, lv);
                    *reinterpret_cast<uint32_t*>(g_hh + base + col) = hv;
                    *reinterpret_cast<uint32_t*>(g_hl + base + col) = lv;
                }
            } else {
                int t  = g_tok[e * MAXROWS + row];
                int kk = g_kslot[e * MAXROWS + row];
                float* outp = g_slot + ((size_t)t * 2 + kk) * EMBED + n0;
#pragma unroll
                for (int ni = 0; ni < 4; ni++) {
                    int col = wn + ni * 8 + 2 * tg;
                    atomicAdd(&outp[col],     acc[mi][ni][rr * 2 + 0]);
                    atomicAdd(&outp[col + 1], acc[mi][ni][rr * 2 + 1]);
                }
            }
        }
    }
}

__global__ void combine_kernel(float* __restrict__ out, const float* __restrict__ b2) {
    int t = blockIdx.x;
    int i = threadIdx.x;  // 256 threads x float4 = 1024 floats
    float w0 = g_topw[t * 2 + 0], w1 = g_topw[t * 2 + 1];
    int e0 = g_expid[t * 2 + 0],  e1 = g_expid[t * 2 + 1];
    float4 a = reinterpret_cast<const float4*>(g_slot + (size_t)t * 2 * EMBED)[i];
    float4 b = reinterpret_cast<const float4*>(g_slot + ((size_t)t * 2 + 1) * EMBED)[i];
    float4 ba = reinterpret_cast<const float4*>(b2 + (size_t)e0 * EMBED)[i];
    float4 bb = reinterpret_cast<const float4*>(b2 + (size_t)e1 * EMBED)[i];
    float4 r;
    r.x = w0 * (a.x + ba.x) + w1 * (b.x + bb.x);
    r.y = w0 * (a.y + ba.y) + w1 * (b.y + bb.y);
    r.z = w0 * (a.z + ba.z) + w1 * (b.z + bb.z);
    r.w = w0 * (a.w + ba.w) + w1 * (b.w + bb.w);
    reinterpret_cast<float4*>(out + (size_t)t * EMBED)[i] = r;
}

// ---------------- launch ----------------
extern "C" void kernel_launch(void* const* d_in, const int* in_sizes, int n_in,
                              void* d_out, int out_size) {
    const float* x   = (const float*)d_in[0];
    const float* gw  = (const float*)d_in[1];
    const float* w1  = (const float*)d_in[2];
    const float* b1  = (const float*)d_in[3];
    const float* w2  = (const float*)d_in[4];
    const float* b2  = (const float*)d_in[5];
    float* out = (float*)d_out;

    constexpr int SMEM_BYTES = (4 * 128 * 40 + 4 * 32 * 136) * 2;  // 75776 B
    cudaFuncSetAttribute(moe_gemm<1>, cudaFuncAttributeMaxDynamicSharedMemorySize, SMEM_BYTES);
    cudaFuncSetAttribute(moe_gemm<2>, cudaFuncAttributeMaxDynamicSharedMemorySize, SMEM_BYTES);

    init_zero_kernel<<<NTOK * 2 * EMBED / 1024, 256>>>();
    router_kernel<<<NTOK / 8, 256>>>(x, gw);

    dim3 grid1(HIDDEN / 128, MAXROWS / 128, NEXP);            // (32, 16, 8)
    moe_gemm<1><<<grid1, 256, SMEM_BYTES>>>(x, w1, b1);

    dim3 grid2(EMBED / 128, MAXROWS / 128, NEXP * KSPLIT2);   // (8, 16, 64)
    moe_gemm<2><<<grid2, 256, SMEM_BYTES>>>(nullptr, w2, b2);

    combine_kernel<<<NTOK, 256>>>(out, b2);
}